// round 1
// baseline (speedup 1.0000x reference)
#include <cuda_runtime.h>
#include <math.h>

// Problem constants
#define BATCH 4
#define HH 48
#define WW 48
#define DD 64
#define HC 46                 // valid patch grid
#define CC 2116               // HC*HC candidate patches
#define MM 2304               // HH*WW locations
#define K9 576                // 9*DD patch dim
#define TEMPR 50.0f

// Scratch (device globals -- no runtime allocation allowed)
static __device__ float g_DS[(size_t)BATCH * MM * CC];   // DS1 then CA in-place (78 MB)
static __device__ float g_bg [BATCH * MM * DD];          // g_in * mask
static __device__ float g_sg [BATCH * MM];               // per-pixel sum g^2
static __device__ float g_sbg[BATCH * MM];               // per-pixel sum bg^2
static __device__ float g_wwd[BATCH * MM];               // 3x3 box sum (same pad) of g_sg
static __device__ float g_k1d[BATCH * CC];               // 3x3 box sum (valid) of g_sbg
static __device__ float g_ACL[BATCH * MM * DD];

// ---------------------------------------------------------------------------
// Kernel 0a: bg = g_in * mask ; per-pixel sums of squares
__global__ void prep_kernel(const float* __restrict__ gin, const float* __restrict__ mask) {
    int p = blockIdx.x;       // b*MM + y*WW + x
    int d = threadIdx.x;      // 0..63
    float mv = mask[p];
    float g  = gin[p * DD + d];
    float bgv = g * mv;
    g_bg[p * DD + d] = bgv;
    __shared__ float s1[DD];
    __shared__ float s2[DD];
    s1[d] = g * g;
    s2[d] = bgv * bgv;
    __syncthreads();
    #pragma unroll
    for (int s = 32; s > 0; s >>= 1) {
        if (d < s) { s1[d] += s1[d + s]; s2[d] += s2[d + s]; }
        __syncthreads();
    }
    if (d == 0) { g_sg[p] = s1[0]; g_sbg[p] = s2[0]; }
}

// Kernel 0b: box sums -> wwd (same pad) and k1d (valid)
__global__ void boxsum_kernel() {
    int idx = blockIdx.x * blockDim.x + threadIdx.x;
    if (idx < BATCH * MM) {
        int b = idx / MM, m = idx - b * MM;
        int y = m / WW, x = m - y * WW;
        float s = 0.f;
        #pragma unroll
        for (int dy = 0; dy < 3; dy++)
            #pragma unroll
            for (int dx = 0; dx < 3; dx++) {
                int yy = y + dy - 1, xx = x + dx - 1;
                if (yy >= 0 && yy < HH && xx >= 0 && xx < WW)
                    s += g_sg[(b * HH + yy) * WW + xx];
            }
        g_wwd[idx] = s;
    } else if (idx < BATCH * MM + BATCH * CC) {
        int id2 = idx - BATCH * MM;
        int b = id2 / CC, j = id2 - b * CC;
        int jy = j / HC, jx = j - jy * HC;
        float s = 0.f;
        #pragma unroll
        for (int dy = 0; dy < 3; dy++)
            #pragma unroll
            for (int dx = 0; dx < 3; dx++)
                s += g_sbg[(b * HH + jy + dy) * WW + jx + dx];
        g_k1d[id2] = s;
    }
}

// ---------------------------------------------------------------------------
// GEMM1: DS1[b,m,n] = k1d[n] + wwd[m] - 2 * sum_k p2[m,k]*p1[n,k]
// Implicit im2col on both operands. 64x64 tile, BK=16, 256 thr, 4x4 microtile.
__global__ __launch_bounds__(256) void gemm1_kernel(const float* __restrict__ gin) {
    __shared__ float As[16][64];
    __shared__ float Bs[16][64];
    int b  = blockIdx.z;
    int m0 = blockIdx.y * 64;
    int n0 = blockIdx.x * 64;
    int tid = threadIdx.x;
    int lk = (tid & 3) * 4;   // k offset within tile (float4)
    int lr = tid >> 2;        // row within tile (0..63)
    int ty = tid >> 4, tx = tid & 15;

    float acc[4][4];
    #pragma unroll
    for (int i = 0; i < 4; i++)
        #pragma unroll
        for (int j = 0; j < 4; j++) acc[i][j] = 0.f;

    int am = m0 + lr;
    int ay = am / WW, ax = am - ay * WW;
    int bn = n0 + lr;
    int bjy = 0, bjx = 0;
    if (bn < CC) { bjy = bn / HC; bjx = bn - bjy * HC; }

    const float* ginb = gin + b * MM * DD;
    const float* bgb  = g_bg + b * MM * DD;

    for (int k0 = 0; k0 < K9; k0 += 16) {
        int kk = k0 + lk;
        int dydx = kk >> 6;
        int ch   = kk & 63;
        int dy = dydx / 3, dx = dydx - dy * 3;

        // A: p2[m, k] = g_in[y+dy-1, x+dx-1, ch] (zero pad)
        float4 va = make_float4(0.f, 0.f, 0.f, 0.f);
        int yy = ay + dy - 1, xx = ax + dx - 1;
        if (yy >= 0 && yy < HH && xx >= 0 && xx < WW)
            va = *(const float4*)(ginb + ((yy * WW + xx) * DD + ch));
        As[lk + 0][lr] = va.x; As[lk + 1][lr] = va.y;
        As[lk + 2][lr] = va.z; As[lk + 3][lr] = va.w;

        // B: p1[n, k] = bg[jy+dy, jx+dx, ch]
        float4 vb = make_float4(0.f, 0.f, 0.f, 0.f);
        if (bn < CC)
            vb = *(const float4*)(bgb + (((bjy + dy) * WW + (bjx + dx)) * DD + ch));
        Bs[lk + 0][lr] = vb.x; Bs[lk + 1][lr] = vb.y;
        Bs[lk + 2][lr] = vb.z; Bs[lk + 3][lr] = vb.w;

        __syncthreads();
        #pragma unroll
        for (int k = 0; k < 16; k++) {
            float4 a4 = *(const float4*)(&As[k][ty * 4]);
            float4 b4 = *(const float4*)(&Bs[k][tx * 4]);
            float av[4] = {a4.x, a4.y, a4.z, a4.w};
            float bv[4] = {b4.x, b4.y, b4.z, b4.w};
            #pragma unroll
            for (int i = 0; i < 4; i++)
                #pragma unroll
                for (int j = 0; j < 4; j++) acc[i][j] += av[i] * bv[j];
        }
        __syncthreads();
    }

    float wv[4];
    #pragma unroll
    for (int i = 0; i < 4; i++) wv[i] = g_wwd[b * MM + m0 + ty * 4 + i];
    #pragma unroll
    for (int j = 0; j < 4; j++) {
        int n = n0 + tx * 4 + j;
        if (n < CC) {
            float kd = g_k1d[b * CC + n];
            #pragma unroll
            for (int i = 0; i < 4; i++) {
                int m = m0 + ty * 4 + i;
                g_DS[(size_t)(b * MM + m) * CC + n] = kd + wv[i] - 2.f * acc[i][j];
            }
        }
    }
}

// ---------------------------------------------------------------------------
// Row softmax with tanh-normalization: in-place on g_DS
__global__ __launch_bounds__(256) void softmax_kernel() {
    __shared__ float srow[CC];
    __shared__ float red[256];
    int row = blockIdx.x;
    float* rp = g_DS + (size_t)row * CC;
    int tid = threadIdx.x;

    float s = 0.f;
    for (int i = tid; i < CC; i += 256) { float v = rp[i]; srow[i] = v; s += v; }
    red[tid] = s; __syncthreads();
    for (int st = 128; st > 0; st >>= 1) { if (tid < st) red[tid] += red[tid + st]; __syncthreads(); }
    float mu = red[0] * (1.0f / CC);
    __syncthreads();

    float s2 = 0.f;
    for (int i = tid; i < CC; i += 256) { float dv = srow[i] - mu; s2 += dv * dv; }
    red[tid] = s2; __syncthreads();
    for (int st = 128; st > 0; st >>= 1) { if (tid < st) red[tid] += red[tid + st]; __syncthreads(); }
    float isd = rsqrtf(red[0] * (1.0f / CC));
    __syncthreads();

    float mx = -1e30f;
    for (int i = tid; i < CC; i += 256) {
        float l = -TEMPR * tanhf((srow[i] - mu) * isd);
        srow[i] = l;
        mx = fmaxf(mx, l);
    }
    red[tid] = mx; __syncthreads();
    for (int st = 128; st > 0; st >>= 1) { if (tid < st) red[tid] = fmaxf(red[tid], red[tid + st]); __syncthreads(); }
    mx = red[0];
    __syncthreads();

    float se = 0.f;
    for (int i = tid; i < CC; i += 256) { float e = __expf(srow[i] - mx); srow[i] = e; se += e; }
    red[tid] = se; __syncthreads();
    for (int st = 128; st > 0; st >>= 1) { if (tid < st) red[tid] += red[tid + st]; __syncthreads(); }
    float inv = 1.0f / red[0];

    for (int i = tid; i < CC; i += 256) rp[i] = srow[i] * inv;
}

// ---------------------------------------------------------------------------
// GEMM2: acl[m,d] = (1/9) sum_{dy,dx} sum_j CA[y+1-dy, x+1-dx, j] * bg[jy+dy, jx+dx, d]
// Epilogue: ACL = bg + acl*(1-mask).  BM=32, BN=64(all d), BK=16, 256 thr, 2x4 microtile.
__global__ __launch_bounds__(256) void gemm2_kernel(const float* __restrict__ mask) {
    __shared__ float As[16][32];
    __shared__ float Bs[16][64];
    int b  = blockIdx.y;
    int m0 = blockIdx.x * 32;
    int tid = threadIdx.x;
    int lk = (tid & 3) * 4, lr = tid >> 2;   // A loaders (tid < 128 active)
    int bd = (tid & 15) * 4, bj = tid >> 4;  // B loaders (all threads)
    int ty = tid >> 4, tx = tid & 15;

    float acc[2][4];
    #pragma unroll
    for (int i = 0; i < 2; i++)
        #pragma unroll
        for (int j = 0; j < 4; j++) acc[i][j] = 0.f;

    int am = m0 + lr;
    int ay = am / WW, ax = am - ay * WW;
    const float* CAb = g_DS + (size_t)b * MM * CC;
    const float* bgb = g_bg + b * MM * DD;

    for (int seg = 0; seg < 9; seg++) {
        int dy = seg / 3, dx = seg - dy * 3;
        int ys = ay + 1 - dy, xs = ax + 1 - dx;
        bool avalid = (lr < 32) && ys >= 0 && ys < HH && xs >= 0 && xs < WW;
        int arow_off = (ys * WW + xs) * CC;   // only used when avalid

        for (int j0 = 0; j0 < CC; j0 += 16) {
            if (lr < 32) {
                float4 va = make_float4(0.f, 0.f, 0.f, 0.f);
                int j = j0 + lk;
                if (avalid && j < CC)
                    va = *(const float4*)(CAb + arow_off + j);
                As[lk + 0][lr] = va.x; As[lk + 1][lr] = va.y;
                As[lk + 2][lr] = va.z; As[lk + 3][lr] = va.w;
            }
            {
                float4 vb = make_float4(0.f, 0.f, 0.f, 0.f);
                int jj = j0 + bj;
                if (jj < CC) {
                    int jy = jj / HC, jx = jj - jy * HC;
                    vb = *(const float4*)(bgb + (((jy + dy) * WW + (jx + dx)) * DD + bd));
                }
                *(float4*)(&Bs[bj][bd]) = vb;
            }
            __syncthreads();
            #pragma unroll
            for (int k = 0; k < 16; k++) {
                float a0 = As[k][ty * 2 + 0];
                float a1 = As[k][ty * 2 + 1];
                float4 b4 = *(const float4*)(&Bs[k][tx * 4]);
                acc[0][0] += a0 * b4.x; acc[0][1] += a0 * b4.y;
                acc[0][2] += a0 * b4.z; acc[0][3] += a0 * b4.w;
                acc[1][0] += a1 * b4.x; acc[1][1] += a1 * b4.y;
                acc[1][2] += a1 * b4.z; acc[1][3] += a1 * b4.w;
            }
            __syncthreads();
        }
    }

    #pragma unroll
    for (int i = 0; i < 2; i++) {
        int row = b * MM + m0 + ty * 2 + i;
        float om = 1.f - mask[row];
        #pragma unroll
        for (int j = 0; j < 4; j++) {
            int idx = row * DD + tx * 4 + j;
            g_ACL[idx] = g_bg[idx] + acc[i][j] * (1.f / 9.f) * om;
        }
    }
}

// ---------------------------------------------------------------------------
// Final: out = elu(concat(g_in, ACL) @ W2 + b2).  4 rows x 64 cols per block.
__global__ __launch_bounds__(256) void final_kernel(const float* __restrict__ gin,
                                                    const float* __restrict__ W2,
                                                    const float* __restrict__ b2,
                                                    float* __restrict__ out) {
    __shared__ float sA[4][128];
    int r0 = blockIdx.x * 4;
    int tid = threadIdx.x;
    for (int idx = tid; idx < 512; idx += 256) {
        int r = idx >> 7, k = idx & 127;
        int row = r0 + r;
        sA[r][k] = (k < DD) ? gin[row * DD + k] : g_ACL[row * DD + (k - DD)];
    }
    __syncthreads();
    int r = tid >> 6, d = tid & 63;
    int row = r0 + r;
    float acc = b2[d];
    #pragma unroll 8
    for (int k = 0; k < 128; k++) acc += sA[r][k] * W2[k * DD + d];
    out[row * DD + d] = (acc > 0.f) ? acc : expm1f(acc);
}

// ---------------------------------------------------------------------------
extern "C" void kernel_launch(void* const* d_in, const int* in_sizes, int n_in,
                              void* d_out, int out_size) {
    const float* gin  = (const float*)d_in[0];
    const float* mask = (const float*)d_in[1];
    const float* W2   = (const float*)d_in[2];
    const float* b2   = (const float*)d_in[3];
    float* out = (float*)d_out;

    prep_kernel<<<BATCH * MM, DD>>>(gin, mask);
    int tot = BATCH * MM + BATCH * CC;
    boxsum_kernel<<<(tot + 255) / 256, 256>>>();
    gemm1_kernel<<<dim3((CC + 63) / 64, MM / 64, BATCH), 256>>>(gin);
    softmax_kernel<<<BATCH * MM, 256>>>();
    gemm2_kernel<<<dim3(MM / 32, BATCH), 256>>>(mask);
    final_kernel<<<BATCH * MM / 4, 256>>>(gin, W2, b2, out);
}

// round 2
// speedup vs baseline: 4.1000x; 4.1000x over previous
#include <cuda_runtime.h>
#include <math.h>

// Problem constants
#define BATCH 4
#define HH 48
#define WW 48
#define DD 64
#define HC 46                 // valid patch grid
#define CC 2116               // HC*HC candidate patches
#define MM 2304               // HH*WW locations
#define TEMPR 50.0f

// Scratch (device globals -- no runtime allocation allowed)
static __device__ float g_E [(size_t)BATCH * MM * MM];   // E Gram, then S (85 MB)
static __device__ float g_DS[(size_t)BATCH * MM * CC];   // CA (78 MB)
static __device__ float g_bg [BATCH * MM * DD];          // g_in * mask
static __device__ float g_sg [BATCH * MM];               // per-pixel sum g^2
static __device__ float g_sbg[BATCH * MM];               // per-pixel sum bg^2
static __device__ float g_wwd[BATCH * MM];               // 3x3 box sum (same pad) of g_sg
static __device__ float g_k1d[BATCH * CC];               // 3x3 box sum (valid) of g_sbg
static __device__ float g_ACL[BATCH * MM * DD];

// ---------------------------------------------------------------------------
// Kernel 0a: bg = g_in * mask ; per-pixel sums of squares
__global__ void prep_kernel(const float* __restrict__ gin, const float* __restrict__ mask) {
    int p = blockIdx.x;       // b*MM + y*WW + x
    int d = threadIdx.x;      // 0..63
    float mv = mask[p];
    float g  = gin[p * DD + d];
    float bgv = g * mv;
    g_bg[p * DD + d] = bgv;
    __shared__ float s1[DD];
    __shared__ float s2[DD];
    s1[d] = g * g;
    s2[d] = bgv * bgv;
    __syncthreads();
    #pragma unroll
    for (int s = 32; s > 0; s >>= 1) {
        if (d < s) { s1[d] += s1[d + s]; s2[d] += s2[d + s]; }
        __syncthreads();
    }
    if (d == 0) { g_sg[p] = s1[0]; g_sbg[p] = s2[0]; }
}

// Kernel 0b: box sums -> wwd (same pad) and k1d (valid)
__global__ void boxsum_kernel() {
    int idx = blockIdx.x * blockDim.x + threadIdx.x;
    if (idx < BATCH * MM) {
        int b = idx / MM, m = idx - b * MM;
        int y = m / WW, x = m - y * WW;
        float s = 0.f;
        #pragma unroll
        for (int dy = 0; dy < 3; dy++)
            #pragma unroll
            for (int dx = 0; dx < 3; dx++) {
                int yy = y + dy - 1, xx = x + dx - 1;
                if (yy >= 0 && yy < HH && xx >= 0 && xx < WW)
                    s += g_sg[(b * HH + yy) * WW + xx];
            }
        g_wwd[idx] = s;
    } else if (idx < BATCH * MM + BATCH * CC) {
        int id2 = idx - BATCH * MM;
        int b = id2 / CC, j = id2 - b * CC;
        int jy = j / HC, jx = j - jy * HC;
        float s = 0.f;
        #pragma unroll
        for (int dy = 0; dy < 3; dy++)
            #pragma unroll
            for (int dx = 0; dx < 3; dx++)
                s += g_sbg[(b * HH + jy + dy) * WW + jx + dx];
        g_k1d[id2] = s;
    }
}

// ---------------------------------------------------------------------------
// gemmE: E[b,p,q] = sum_ch gin[b,p,ch] * bg[b,q,ch].  M=N=2304, K=64.
// 64x64 tile, BK=16, 256 threads, 4x4 microtile.
__global__ __launch_bounds__(256) void gemmE_kernel(const float* __restrict__ gin) {
    __shared__ float As[16][64];
    __shared__ float Bs[16][64];
    int b  = blockIdx.z;
    int p0 = blockIdx.y * 64;
    int q0 = blockIdx.x * 64;
    int tid = threadIdx.x;
    int lk = (tid & 3) * 4;
    int lr = tid >> 2;
    int ty = tid >> 4, tx = tid & 15;

    const float* A = gin  + (size_t)b * MM * DD;
    const float* B = g_bg + (size_t)b * MM * DD;

    float acc[4][4];
    #pragma unroll
    for (int i = 0; i < 4; i++)
        #pragma unroll
        for (int j = 0; j < 4; j++) acc[i][j] = 0.f;

    #pragma unroll
    for (int k0 = 0; k0 < DD; k0 += 16) {
        float4 va = *(const float4*)(A + (p0 + lr) * DD + k0 + lk);
        As[lk + 0][lr] = va.x; As[lk + 1][lr] = va.y;
        As[lk + 2][lr] = va.z; As[lk + 3][lr] = va.w;
        float4 vb = *(const float4*)(B + (q0 + lr) * DD + k0 + lk);
        Bs[lk + 0][lr] = vb.x; Bs[lk + 1][lr] = vb.y;
        Bs[lk + 2][lr] = vb.z; Bs[lk + 3][lr] = vb.w;
        __syncthreads();
        #pragma unroll
        for (int k = 0; k < 16; k++) {
            float4 a4 = *(const float4*)(&As[k][ty * 4]);
            float4 b4 = *(const float4*)(&Bs[k][tx * 4]);
            float av[4] = {a4.x, a4.y, a4.z, a4.w};
            float bv[4] = {b4.x, b4.y, b4.z, b4.w};
            #pragma unroll
            for (int i = 0; i < 4; i++)
                #pragma unroll
                for (int j = 0; j < 4; j++) acc[i][j] += av[i] * bv[j];
        }
        __syncthreads();
    }

    float* Eb = g_E + (size_t)b * MM * MM;
    #pragma unroll
    for (int i = 0; i < 4; i++) {
        float4 v;
        v.x = acc[i][0]; v.y = acc[i][1]; v.z = acc[i][2]; v.w = acc[i][3];
        *(float4*)(Eb + (size_t)(p0 + ty * 4 + i) * MM + q0 + tx * 4) = v;
    }
}

// ---------------------------------------------------------------------------
// Fused DS + tanh-normalized softmax.  One CTA per output row m.
// CS[m,n] = sum_{dy,dx} E[(y+dy-1,x+dx-1), (jy+dy,jx+dx)]  (tap dropped if p OOB)
// DS1 = k1d[n] + wwd[m] - 2*CS ; then softmax(-TEMP*tanh((DS1-mu)/sd)).
__global__ __launch_bounds__(256) void ds_softmax_kernel() {
    __shared__ float srow[CC];
    __shared__ float red[256];
    int row = blockIdx.x;
    int b = row / MM, m = row - b * MM;
    int y = m / WW, x = m - y * WW;
    int tid = threadIdx.x;

    const float* Eb = g_E + (size_t)b * MM * MM;
    const float* tp[9];
    bool tv[9];
    #pragma unroll
    for (int t = 0; t < 9; t++) {
        int dy = t / 3, dx = t - dy * 3;
        int yy = y + dy - 1, xx = x + dx - 1;
        tv[t] = (yy >= 0 && yy < HH && xx >= 0 && xx < WW);
        int pp = tv[t] ? (yy * WW + xx) : 0;
        tp[t] = Eb + (size_t)pp * MM + (dy * WW + dx);
    }
    float wv = g_wwd[row];
    const float* k1 = g_k1d + b * CC;

    float s = 0.f;
    for (int n = tid; n < CC; n += 256) {
        int jy = n / HC, jx = n - jy * HC;
        int qb = jy * WW + jx;
        float cs = 0.f;
        #pragma unroll
        for (int t = 0; t < 9; t++)
            if (tv[t]) cs += tp[t][qb];
        float v = k1[n] + wv - 2.f * cs;
        srow[n] = v;
        s += v;
    }
    red[tid] = s; __syncthreads();
    for (int st = 128; st > 0; st >>= 1) { if (tid < st) red[tid] += red[tid + st]; __syncthreads(); }
    float mu = red[0] * (1.0f / CC);
    __syncthreads();

    float s2 = 0.f;
    for (int i = tid; i < CC; i += 256) { float dv = srow[i] - mu; s2 += dv * dv; }
    red[tid] = s2; __syncthreads();
    for (int st = 128; st > 0; st >>= 1) { if (tid < st) red[tid] += red[tid + st]; __syncthreads(); }
    float isd = rsqrtf(red[0] * (1.0f / CC));
    __syncthreads();

    float mx = -1e30f;
    for (int i = tid; i < CC; i += 256) {
        float l = -TEMPR * tanhf((srow[i] - mu) * isd);
        srow[i] = l;
        mx = fmaxf(mx, l);
    }
    red[tid] = mx; __syncthreads();
    for (int st = 128; st > 0; st >>= 1) { if (tid < st) red[tid] = fmaxf(red[tid], red[tid + st]); __syncthreads(); }
    mx = red[0];
    __syncthreads();

    float se = 0.f;
    for (int i = tid; i < CC; i += 256) { float e = __expf(srow[i] - mx); srow[i] = e; se += e; }
    red[tid] = se; __syncthreads();
    for (int st = 128; st > 0; st >>= 1) { if (tid < st) red[tid] += red[tid + st]; __syncthreads(); }
    float inv = 1.0f / red[0];

    float* rp = g_DS + (size_t)row * CC;
    for (int i = tid; i < CC; i += 256) rp[i] = srow[i] * inv;
}

// ---------------------------------------------------------------------------
// S gather: S[b,m,q] = sum_{dy,dx} CA[(y+1-dy, x+1-dx), (qy-dy)*46 + (qx-dx)]
// valid when both the m' grid coords and the (jy,jx) patch coords are in range.
// Writes into g_E (E is dead after ds_softmax).  One CTA per row m.
__global__ __launch_bounds__(256) void s_gather_kernel() {
    int row = blockIdx.x;
    int b = row / MM, m = row - b * MM;
    int y = m / WW, x = m - y * WW;
    int tid = threadIdx.x;

    const float* CAb = g_DS + (size_t)b * MM * CC;
    const float* tp[9];
    bool tv[9];
    #pragma unroll
    for (int t = 0; t < 9; t++) {
        int dy = t / 3, dx = t - dy * 3;
        int yy = y + 1 - dy, xx = x + 1 - dx;
        tv[t] = (yy >= 0 && yy < HH && xx >= 0 && xx < WW);
        int mp = tv[t] ? (yy * WW + xx) : 0;
        tp[t] = CAb + (size_t)mp * CC - (dy * HC + dx);
    }

    float* Sout = g_E + (size_t)b * MM * MM + (size_t)m * MM;
    for (int q = tid; q < MM; q += 256) {
        int qy = q / WW, qx = q - qy * WW;
        int base = qy * HC + qx;
        float s = 0.f;
        #pragma unroll
        for (int t = 0; t < 9; t++) {
            int dy = t / 3, dx = t - dy * 3;
            if (tv[t] && (unsigned)(qy - dy) < HC && (unsigned)(qx - dx) < HC)
                s += tp[t][base];
        }
        Sout[q] = s;
    }
}

// ---------------------------------------------------------------------------
// gemm_acl: acl[m,d] = sum_q S[m,q] * bg[q,d]; ACL = bg + acl/9*(1-mask).
// M=2304, K=2304, N=64.  BM=64, BN=64, BK=16, 256 threads, 4x4 micro.
__global__ __launch_bounds__(256) void gemm_acl_kernel(const float* __restrict__ mask) {
    __shared__ float As[16][64];
    __shared__ float Bs[16][64];
    int b  = blockIdx.y;
    int m0 = blockIdx.x * 64;
    int tid = threadIdx.x;
    int lk = (tid & 3) * 4;
    int lr = tid >> 2;
    int bj = tid >> 4, bd = (tid & 15) * 4;
    int ty = tid >> 4, tx = tid & 15;

    const float* Sb  = g_E  + (size_t)b * MM * MM;
    const float* bgb = g_bg + (size_t)b * MM * DD;

    float acc[4][4];
    #pragma unroll
    for (int i = 0; i < 4; i++)
        #pragma unroll
        for (int j = 0; j < 4; j++) acc[i][j] = 0.f;

    for (int k0 = 0; k0 < MM; k0 += 16) {
        float4 va = *(const float4*)(Sb + (size_t)(m0 + lr) * MM + k0 + lk);
        As[lk + 0][lr] = va.x; As[lk + 1][lr] = va.y;
        As[lk + 2][lr] = va.z; As[lk + 3][lr] = va.w;
        float4 vb = *(const float4*)(bgb + (k0 + bj) * DD + bd);
        *(float4*)(&Bs[bj][bd]) = vb;
        __syncthreads();
        #pragma unroll
        for (int k = 0; k < 16; k++) {
            float4 a4 = *(const float4*)(&As[k][ty * 4]);
            float4 b4 = *(const float4*)(&Bs[k][tx * 4]);
            float av[4] = {a4.x, a4.y, a4.z, a4.w};
            float bv[4] = {b4.x, b4.y, b4.z, b4.w};
            #pragma unroll
            for (int i = 0; i < 4; i++)
                #pragma unroll
                for (int j = 0; j < 4; j++) acc[i][j] += av[i] * bv[j];
        }
        __syncthreads();
    }

    #pragma unroll
    for (int i = 0; i < 4; i++) {
        int rowm = b * MM + m0 + ty * 4 + i;
        float om = (1.f - mask[rowm]) * (1.f / 9.f);
        #pragma unroll
        for (int j = 0; j < 4; j++) {
            int idx = rowm * DD + tx * 4 + j;
            g_ACL[idx] = g_bg[idx] + acc[i][j] * om;
        }
    }
}

// ---------------------------------------------------------------------------
// Final: out = elu(concat(g_in, ACL) @ W2 + b2).  4 rows x 64 cols per block.
__global__ __launch_bounds__(256) void final_kernel(const float* __restrict__ gin,
                                                    const float* __restrict__ W2,
                                                    const float* __restrict__ b2,
                                                    float* __restrict__ out) {
    __shared__ float sA[4][128];
    int r0 = blockIdx.x * 4;
    int tid = threadIdx.x;
    for (int idx = tid; idx < 512; idx += 256) {
        int r = idx >> 7, k = idx & 127;
        int row = r0 + r;
        sA[r][k] = (k < DD) ? gin[row * DD + k] : g_ACL[row * DD + (k - DD)];
    }
    __syncthreads();
    int r = tid >> 6, d = tid & 63;
    int row = r0 + r;
    float acc = b2[d];
    #pragma unroll 8
    for (int k = 0; k < 128; k++) acc += sA[r][k] * W2[k * DD + d];
    out[row * DD + d] = (acc > 0.f) ? acc : expm1f(acc);
}

// ---------------------------------------------------------------------------
extern "C" void kernel_launch(void* const* d_in, const int* in_sizes, int n_in,
                              void* d_out, int out_size) {
    const float* gin  = (const float*)d_in[0];
    const float* mask = (const float*)d_in[1];
    const float* W2   = (const float*)d_in[2];
    const float* b2   = (const float*)d_in[3];
    float* out = (float*)d_out;

    prep_kernel<<<BATCH * MM, DD>>>(gin, mask);
    int tot = BATCH * MM + BATCH * CC;
    boxsum_kernel<<<(tot + 255) / 256, 256>>>();
    gemmE_kernel<<<dim3(MM / 64, MM / 64, BATCH), 256>>>(gin);
    ds_softmax_kernel<<<BATCH * MM, 256>>>();
    s_gather_kernel<<<BATCH * MM, 256>>>();
    gemm_acl_kernel<<<dim3(MM / 64, BATCH), 256>>>(mask);
    final_kernel<<<BATCH * MM / 4, 256>>>(gin, W2, b2, out);
}

// round 3
// speedup vs baseline: 4.9818x; 1.2151x over previous
#include <cuda_runtime.h>
#include <math.h>
#include <stddef.h>

// Problem constants
#define BATCH 4
#define HH 48
#define WW 48
#define DD 64
#define HC 46                 // valid patch grid
#define CC 2116               // HC*HC candidate patches
#define MM 2304               // HH*WW locations
#define TEMPR 50.0f

// Scratch (device globals -- no runtime allocation allowed)
static __device__ float g_E [(size_t)BATCH * MM * MM];   // E Gram, then S (85 MB)
static __device__ float g_DS[(size_t)BATCH * MM * CC];   // CA (78 MB)
static __device__ float g_bg [BATCH * MM * DD];          // g_in * mask
static __device__ float g_sg [BATCH * MM];               // per-pixel sum g^2
static __device__ float g_sbg[BATCH * MM];               // per-pixel sum bg^2
static __device__ float g_wwd[BATCH * MM];               // 3x3 box sum (same pad) of g_sg
static __device__ float g_k1d[BATCH * CC];               // 3x3 box sum (valid) of g_sbg
static __device__ float g_ACL[BATCH * MM * DD];

// ---------------------------------------------------------------------------
// Kernel 0a: bg = g_in * mask ; per-pixel sums of squares
__global__ void prep_kernel(const float* __restrict__ gin, const float* __restrict__ mask) {
    int p = blockIdx.x;
    int d = threadIdx.x;
    float mv = mask[p];
    float g  = gin[p * DD + d];
    float bgv = g * mv;
    g_bg[p * DD + d] = bgv;
    __shared__ float s1[DD];
    __shared__ float s2[DD];
    s1[d] = g * g;
    s2[d] = bgv * bgv;
    __syncthreads();
    #pragma unroll
    for (int s = 32; s > 0; s >>= 1) {
        if (d < s) { s1[d] += s1[d + s]; s2[d] += s2[d + s]; }
        __syncthreads();
    }
    if (d == 0) { g_sg[p] = s1[0]; g_sbg[p] = s2[0]; }
}

// Kernel 0b: box sums -> wwd (same pad) and k1d (valid)
__global__ void boxsum_kernel() {
    int idx = blockIdx.x * blockDim.x + threadIdx.x;
    if (idx < BATCH * MM) {
        int b = idx / MM, m = idx - b * MM;
        int y = m / WW, x = m - y * WW;
        float s = 0.f;
        #pragma unroll
        for (int dy = 0; dy < 3; dy++)
            #pragma unroll
            for (int dx = 0; dx < 3; dx++) {
                int yy = y + dy - 1, xx = x + dx - 1;
                if (yy >= 0 && yy < HH && xx >= 0 && xx < WW)
                    s += g_sg[(b * HH + yy) * WW + xx];
            }
        g_wwd[idx] = s;
    } else if (idx < BATCH * MM + BATCH * CC) {
        int id2 = idx - BATCH * MM;
        int b = id2 / CC, j = id2 - b * CC;
        int jy = j / HC, jx = j - jy * HC;
        float s = 0.f;
        #pragma unroll
        for (int dy = 0; dy < 3; dy++)
            #pragma unroll
            for (int dx = 0; dx < 3; dx++)
                s += g_sbg[(b * HH + jy + dy) * WW + jx + dx];
        g_k1d[id2] = s;
    }
}

// ---------------------------------------------------------------------------
// gemmE: E[b,p,q] = sum_ch gin[b,p,ch] * bg[b,q,ch].  M=N=2304, K=64.
__global__ __launch_bounds__(256) void gemmE_kernel(const float* __restrict__ gin) {
    __shared__ float As[16][64];
    __shared__ float Bs[16][64];
    int b  = blockIdx.z;
    int p0 = blockIdx.y * 64;
    int q0 = blockIdx.x * 64;
    int tid = threadIdx.x;
    int lk = (tid & 3) * 4;
    int lr = tid >> 2;
    int ty = tid >> 4, tx = tid & 15;

    const float* A = gin  + (size_t)b * MM * DD;
    const float* B = g_bg + (size_t)b * MM * DD;

    float acc[4][4];
    #pragma unroll
    for (int i = 0; i < 4; i++)
        #pragma unroll
        for (int j = 0; j < 4; j++) acc[i][j] = 0.f;

    #pragma unroll
    for (int k0 = 0; k0 < DD; k0 += 16) {
        float4 va = *(const float4*)(A + (p0 + lr) * DD + k0 + lk);
        As[lk + 0][lr] = va.x; As[lk + 1][lr] = va.y;
        As[lk + 2][lr] = va.z; As[lk + 3][lr] = va.w;
        float4 vb = *(const float4*)(B + (q0 + lr) * DD + k0 + lk);
        Bs[lk + 0][lr] = vb.x; Bs[lk + 1][lr] = vb.y;
        Bs[lk + 2][lr] = vb.z; Bs[lk + 3][lr] = vb.w;
        __syncthreads();
        #pragma unroll
        for (int k = 0; k < 16; k++) {
            float4 a4 = *(const float4*)(&As[k][ty * 4]);
            float4 b4 = *(const float4*)(&Bs[k][tx * 4]);
            float av[4] = {a4.x, a4.y, a4.z, a4.w};
            float bv[4] = {b4.x, b4.y, b4.z, b4.w};
            #pragma unroll
            for (int i = 0; i < 4; i++)
                #pragma unroll
                for (int j = 0; j < 4; j++) acc[i][j] += av[i] * bv[j];
        }
        __syncthreads();
    }

    float* Eb = g_E + (size_t)b * MM * MM;
    #pragma unroll
    for (int i = 0; i < 4; i++) {
        float4 v;
        v.x = acc[i][0]; v.y = acc[i][1]; v.z = acc[i][2]; v.w = acc[i][3];
        *(float4*)(Eb + (size_t)(p0 + ty * 4 + i) * MM + q0 + tx * 4) = v;
    }
}

// ---------------------------------------------------------------------------
// Block-wide sum over 256 threads via shuffle + 8-slot smem.
__device__ __forceinline__ float block_sum256(float v, float* red) {
    int tid = threadIdx.x;
    #pragma unroll
    for (int o = 16; o > 0; o >>= 1) v += __shfl_xor_sync(0xffffffffu, v, o);
    __syncthreads();                 // protect red from previous use
    if ((tid & 31) == 0) red[tid >> 5] = v;
    __syncthreads();
    float tot = red[0] + red[1] + red[2] + red[3] + red[4] + red[5] + red[6] + red[7];
    return tot;
}

// ---------------------------------------------------------------------------
// Fused DS + tanh-normalized softmax.  One CTA per output row m.
// All 9 tap addresses = base + qb + (dy*48+dx)*(MM+1)  (compile-time tap consts).
// Register-resident row (9 elems/thread, stride 256). No max pass: logits in
// [-50,50] so exp() is safe unshifted. tanh+exp fused via exp identities.
__global__ __launch_bounds__(256) void ds_softmax_kernel() {
    __shared__ float red[8];
    int row = blockIdx.x;
    int b = row / MM, m = row - b * MM;
    int y = m / WW, x = m - y * WW;
    int tid = threadIdx.x;

    const float* Eb = g_E + (size_t)b * MM * MM;
    const float* base = Eb + (ptrdiff_t)((y - 1) * WW + (x - 1)) * MM;
    float wv = g_wwd[row];
    const float* k1 = g_k1d + b * CC;

    bool tvy[3], tvx[3];
    #pragma unroll
    for (int t = 0; t < 3; t++) {
        tvy[t] = (unsigned)(y + t - 1) < (unsigned)HH;
        tvx[t] = (unsigned)(x + t - 1) < (unsigned)WW;
    }
    bool interior = tvy[0] && tvy[2] && tvx[0] && tvx[2];

    float v[9];
    float s = 0.f;

    if (interior) {
        #pragma unroll
        for (int i = 0; i < 9; i++) {
            int n = tid + 256 * i;
            if (n < CC) {
                int jy = n / HC, jx = n - jy * HC;
                const float* p = base + (jy * WW + jx);
                float cs = 0.f;
                #pragma unroll
                for (int dy = 0; dy < 3; dy++)
                    #pragma unroll
                    for (int dx = 0; dx < 3; dx++)
                        cs += p[(dy * WW + dx) * (MM + 1)];
                float val = fmaf(-2.f, cs, k1[n] + wv);
                v[i] = val;
                s += val;
            } else v[i] = 0.f;
        }
    } else {
        #pragma unroll
        for (int i = 0; i < 9; i++) {
            int n = tid + 256 * i;
            if (n < CC) {
                int jy = n / HC, jx = n - jy * HC;
                const float* p = base + (jy * WW + jx);
                float cs = 0.f;
                #pragma unroll
                for (int dy = 0; dy < 3; dy++)
                    #pragma unroll
                    for (int dx = 0; dx < 3; dx++)
                        if (tvy[dy] && tvx[dx])
                            cs += p[(dy * WW + dx) * (MM + 1)];
                float val = fmaf(-2.f, cs, k1[n] + wv);
                v[i] = val;
                s += val;
            } else v[i] = 0.f;
        }
    }

    float mu = block_sum256(s, red) * (1.0f / CC);

    float s2 = 0.f;
    #pragma unroll
    for (int i = 0; i < 9; i++) {
        int n = tid + 256 * i;
        if (n < CC) { float d = v[i] - mu; s2 = fmaf(d, d, s2); }
    }
    float isd = rsqrtf(block_sum256(s2, red) * (1.0f / CC));

    // e = exp(-TEMP*tanh(w)) = exp(100/(e^{2w}+1) - 50),  w=(v-mu)*isd
    float se = 0.f;
    #pragma unroll
    for (int i = 0; i < 9; i++) {
        int n = tid + 256 * i;
        if (n < CC) {
            float w = (v[i] - mu) * isd;
            float u = __expf(2.f * w);
            float e = __expf(__fdividef(100.f, u + 1.f) - 50.f);
            v[i] = e;
            se += e;
        }
    }
    float inv = 1.0f / block_sum256(se, red);

    float* rp = g_DS + (size_t)row * CC;
    #pragma unroll
    for (int i = 0; i < 9; i++) {
        int n = tid + 256 * i;
        if (n < CC) rp[n] = v[i] * inv;
    }
}

// ---------------------------------------------------------------------------
// S gather: S[b,m,q] = sum_{dy,dx} CA[(y+1-dy, x+1-dx), (qy-dy)*46 + (qx-dx)]
// All tap addresses = basep + (qy*46+qx) - dy*101614 - dx*2117 (compile-time).
__global__ __launch_bounds__(256) void s_gather_kernel() {
    int row = blockIdx.x;
    int b = row / MM, m = row - b * MM;
    int y = m / WW, x = m - y * WW;
    int tid = threadIdx.x;

    const float* CAb = g_DS + (size_t)b * MM * CC;
    const float* basep = CAb + (ptrdiff_t)((y + 1) * WW + (x + 1)) * CC;

    bool tvy[3], tvx[3];
    #pragma unroll
    for (int t = 0; t < 3; t++) {
        tvy[t] = (unsigned)(y + 1 - t) < (unsigned)HH;
        tvx[t] = (unsigned)(x + 1 - t) < (unsigned)WW;
    }
    bool interior_m = tvy[2] && tvx[2] && tvy[0] && tvx[0]; // y,x in [1,46]

    float* Sout = g_E + (size_t)b * MM * MM + (size_t)m * MM;

    if (interior_m) {
        for (int q = tid; q < MM; q += 256) {
            int qy = q / WW, qx = q - qy * WW;
            const float* p = basep + (qy * HC + qx);
            float s = 0.f;
            if (qy >= 2 && qy <= 45 && qx >= 2 && qx <= 45) {
                #pragma unroll
                for (int dy = 0; dy < 3; dy++)
                    #pragma unroll
                    for (int dx = 0; dx < 3; dx++)
                        s += p[-(dy * (WW * CC + HC) + dx * (CC + 1))];
            } else {
                #pragma unroll
                for (int dy = 0; dy < 3; dy++)
                    #pragma unroll
                    for (int dx = 0; dx < 3; dx++)
                        if ((unsigned)(qy - dy) < (unsigned)HC &&
                            (unsigned)(qx - dx) < (unsigned)HC)
                            s += p[-(dy * (WW * CC + HC) + dx * (CC + 1))];
            }
            Sout[q] = s;
        }
    } else {
        for (int q = tid; q < MM; q += 256) {
            int qy = q / WW, qx = q - qy * WW;
            const float* p = basep + (qy * HC + qx);
            float s = 0.f;
            #pragma unroll
            for (int dy = 0; dy < 3; dy++)
                #pragma unroll
                for (int dx = 0; dx < 3; dx++)
                    if (tvy[dy] && tvx[dx] &&
                        (unsigned)(qy - dy) < (unsigned)HC &&
                        (unsigned)(qx - dx) < (unsigned)HC)
                        s += p[-(dy * (WW * CC + HC) + dx * (CC + 1))];
            Sout[q] = s;
        }
    }
}

// ---------------------------------------------------------------------------
// gemm_acl: acl[m,d] = sum_q S[m,q] * bg[q,d]; ACL = bg + acl/9*(1-mask).
__global__ __launch_bounds__(256) void gemm_acl_kernel(const float* __restrict__ mask) {
    __shared__ float As[16][64];
    __shared__ float Bs[16][64];
    int b  = blockIdx.y;
    int m0 = blockIdx.x * 64;
    int tid = threadIdx.x;
    int lk = (tid & 3) * 4;
    int lr = tid >> 2;
    int bj = tid >> 4, bd = (tid & 15) * 4;
    int ty = tid >> 4, tx = tid & 15;

    const float* Sb  = g_E  + (size_t)b * MM * MM;
    const float* bgb = g_bg + (size_t)b * MM * DD;

    float acc[4][4];
    #pragma unroll
    for (int i = 0; i < 4; i++)
        #pragma unroll
        for (int j = 0; j < 4; j++) acc[i][j] = 0.f;

    for (int k0 = 0; k0 < MM; k0 += 16) {
        float4 va = *(const float4*)(Sb + (size_t)(m0 + lr) * MM + k0 + lk);
        As[lk + 0][lr] = va.x; As[lk + 1][lr] = va.y;
        As[lk + 2][lr] = va.z; As[lk + 3][lr] = va.w;
        float4 vb = *(const float4*)(bgb + (k0 + bj) * DD + bd);
        *(float4*)(&Bs[bj][bd]) = vb;
        __syncthreads();
        #pragma unroll
        for (int k = 0; k < 16; k++) {
            float4 a4 = *(const float4*)(&As[k][ty * 4]);
            float4 b4 = *(const float4*)(&Bs[k][tx * 4]);
            float av[4] = {a4.x, a4.y, a4.z, a4.w};
            float bv[4] = {b4.x, b4.y, b4.z, b4.w};
            #pragma unroll
            for (int i = 0; i < 4; i++)
                #pragma unroll
                for (int j = 0; j < 4; j++) acc[i][j] += av[i] * bv[j];
        }
        __syncthreads();
    }

    #pragma unroll
    for (int i = 0; i < 4; i++) {
        int rowm = b * MM + m0 + ty * 4 + i;
        float om = (1.f - mask[rowm]) * (1.f / 9.f);
        #pragma unroll
        for (int j = 0; j < 4; j++) {
            int idx = rowm * DD + tx * 4 + j;
            g_ACL[idx] = g_bg[idx] + acc[i][j] * om;
        }
    }
}

// ---------------------------------------------------------------------------
// Final: out = elu(concat(g_in, ACL) @ W2 + b2).  4 rows x 64 cols per block.
__global__ __launch_bounds__(256) void final_kernel(const float* __restrict__ gin,
                                                    const float* __restrict__ W2,
                                                    const float* __restrict__ b2,
                                                    float* __restrict__ out) {
    __shared__ float sA[4][128];
    int r0 = blockIdx.x * 4;
    int tid = threadIdx.x;
    for (int idx = tid; idx < 512; idx += 256) {
        int r = idx >> 7, k = idx & 127;
        int row = r0 + r;
        sA[r][k] = (k < DD) ? gin[row * DD + k] : g_ACL[row * DD + (k - DD)];
    }
    __syncthreads();
    int r = tid >> 6, d = tid & 63;
    int row = r0 + r;
    float acc = b2[d];
    #pragma unroll 8
    for (int k = 0; k < 128; k++) acc += sA[r][k] * W2[k * DD + d];
    out[row * DD + d] = (acc > 0.f) ? acc : expm1f(acc);
}

// ---------------------------------------------------------------------------
extern "C" void kernel_launch(void* const* d_in, const int* in_sizes, int n_in,
                              void* d_out, int out_size) {
    const float* gin  = (const float*)d_in[0];
    const float* mask = (const float*)d_in[1];
    const float* W2   = (const float*)d_in[2];
    const float* b2   = (const float*)d_in[3];
    float* out = (float*)d_out;

    prep_kernel<<<BATCH * MM, DD>>>(gin, mask);
    int tot = BATCH * MM + BATCH * CC;
    boxsum_kernel<<<(tot + 255) / 256, 256>>>();
    gemmE_kernel<<<dim3(MM / 64, MM / 64, BATCH), 256>>>(gin);
    ds_softmax_kernel<<<BATCH * MM, 256>>>();
    s_gather_kernel<<<BATCH * MM, 256>>>();
    gemm_acl_kernel<<<dim3(MM / 64, BATCH), 256>>>(mask);
    final_kernel<<<BATCH * MM / 4, 256>>>(gin, W2, b2, out);
}